// round 8
// baseline (speedup 1.0000x reference)
#include <cuda_runtime.h>
#include <math.h>

#define NB 32
#define HW 16384

typedef unsigned long long u64;

__device__ __forceinline__ u64 fma2(u64 a, u64 b, u64 c) {
    u64 d;
    asm("fma.rn.f32x2 %0, %1, %2, %3;" : "=l"(d) : "l"(a), "l"(b), "l"(c));
    return d;
}
__device__ __forceinline__ u64 mul2(u64 a, u64 b) {
    u64 d;
    asm("mul.rn.f32x2 %0, %1, %2;" : "=l"(d) : "l"(a), "l"(b));
    return d;
}
__device__ __forceinline__ u64 add2(u64 a, u64 b) {
    u64 d;
    asm("add.rn.f32x2 %0, %1, %2;" : "=l"(d) : "l"(a), "l"(b));
    return d;
}
__device__ __forceinline__ u64 neg2(u64 a) { return a ^ 0x8000000080000000ull; }
__device__ __forceinline__ u64 pk(float lo, float hi) {
    u64 d;
    asm("mov.b64 %0, {%1, %2};" : "=l"(d) : "f"(lo), "f"(hi));
    return d;
}

__device__ __forceinline__ float2 cmulc(float2 a, float2 b) {
    return make_float2(fmaf(a.x, b.x, -a.y * b.y), fmaf(a.x, b.y, a.y * b.x));
}
__device__ __forceinline__ float2 cfmac(float2 a, float2 b, float2 c) {
    c.x = fmaf(a.x, b.x, fmaf(-a.y, b.y, c.x));
    c.y = fmaf(a.x, b.y, fmaf(a.y, b.x, c.y));
    return c;
}

// cos/sin(pi*r/7), r = 0..13
__constant__ float HC[14] = {
    1.f,  0.90096886790f,  0.62348980185f,  0.22252093396f,
    -0.22252093396f, -0.62348980185f, -0.90096886790f, -1.f,
    -0.90096886790f, -0.62348980185f, -0.22252093396f,
    0.22252093396f,  0.62348980185f,  0.90096886790f };
__constant__ float HS[14] = {
    0.f,  0.43388373912f,  0.78183148246f,  0.97492791218f,
    0.97492791218f,  0.78183148246f,  0.43388373912f,  0.f,
    -0.43388373912f, -0.78183148246f, -0.97492791218f,
    -0.97492791218f, -0.78183148246f, -0.43388373912f };
// twiddle e^{-2*pi*i*k/7}
__constant__ float TWC[7] = {
    1.f, 0.62348980185f, -0.22252093396f, -0.90096886790f,
    -0.90096886790f, -0.22252093396f, 0.62348980185f };
__constant__ float TWS[7] = {
    0.f, -0.78183148246f, -0.97492791218f, -0.43388373912f,
    0.43388373912f, 0.97492791218f, 0.78183148246f };

// ---------------------------------------------------------------------------
// Packed evaluation of one element pair; coefficients read from shared mem.
// sh_g layout (u64[50], each value duplicated in both halves):
//  [0] c00
//  [1+2(n-1)] qr_n   [2+2(n-1)] -qi_n                     (n=1..3)
//  base=7+14(m-1): [base] t0r  [base+1] t0i
//  [base+2+4(n-1)+{0..3}] = Pr, -Mi, Pi, Mr               (n=1..3)
// ---------------------------------------------------------------------------
__device__ __forceinline__ u64 eval_pair(float4 xv, const u64* __restrict__ C) {
    const u64 NEG1 = 0xBF800000BF800000ull;

    float s0a, c0a, s1a, c1a, s0b, c0b, s1b, c1b;
    __sincosf(xv.x, &s0a, &c0a);
    __sincosf(xv.y, &s1a, &c1a);
    __sincosf(xv.z, &s0b, &c0b);
    __sincosf(xv.w, &s1b, &c1b);

    u64 c0 = pk(c0a, c0b), s0 = pk(s0a, s0b);
    u64 c1 = pk(c1a, c1b), s1 = pk(s1a, s1b);

    u64 tc0 = add2(c0, c0), tc1 = add2(c1, c1);
    u64 cw2 = fma2(tc0, c0, NEG1);
    u64 nsw1 = neg2(s0);
    u64 nsw2 = mul2(tc0, nsw1);
    u64 cw3 = fma2(tc0, cw2, neg2(c0));
    u64 nsw3 = fma2(tc0, nsw2, s0);
    u64 cz2 = fma2(tc1, c1, NEG1);
    u64 sz2 = mul2(tc1, s1);
    u64 cz3 = fma2(tc1, cz2, neg2(c1));
    u64 sz3 = fma2(tc1, sz2, neg2(s1));

    u64 cz[3] = {c1, cz2, cz3};
    u64 sz[3] = {s1, sz2, sz3};
    u64 cw[3] = {c0, cw2, cw3};
    u64 nsw[3] = {nsw1, nsw2, nsw3};

    u64 ev0 = C[0];
    u64 ev1 = fma2(C[1], cz[0], mul2(C[2], sz[0]));
#pragma unroll
    for (int n = 1; n < 3; ++n) {
        ev0 = fma2(C[1 + 2 * n], cz[n], ev0);
        ev1 = fma2(C[2 + 2 * n], sz[n], ev1);
    }
#pragma unroll
    for (int m = 0; m < 3; ++m) {
        const int base = 7 + 14 * m;
        u64 hx = C[base], hy = C[base + 1];
#pragma unroll
        for (int n = 0; n < 3; ++n) {
            const int q = base + 2 + 4 * n;
            hx = fma2(C[q + 0], cz[n], hx);
            hx = fma2(C[q + 1], sz[n], hx);
            hy = fma2(C[q + 2], cz[n], hy);
            hy = fma2(C[q + 3], sz[n], hy);
        }
        if (m & 1) { ev1 = fma2(cw[m], hx, ev1); ev1 = fma2(nsw[m], hy, ev1); }
        else       { ev0 = fma2(cw[m], hx, ev0); ev0 = fma2(nsw[m], hy, ev0); }
    }
    return add2(ev0, ev1);
}

// ---------------------------------------------------------------------------
// Fused kernel: in-block coefficient setup (smem), then eval 1024 elements.
// 256 threads, 2 packed pairs/thread, 64-reg cap via launch_bounds.
// ---------------------------------------------------------------------------
__global__ void __launch_bounds__(256, 4)
qlayer_fused(const float* __restrict__ x, const float* __restrict__ qstyles,
             float* __restrict__ out) {
    const int b = blockIdx.y;
    const int t = threadIdx.x;

    __shared__ float2 shU[16][4];
    __shared__ float2 shM[4][16];
    __shared__ float sh_ev[49];
    __shared__ float2 sh_c[4][7];
    __shared__ __align__(16) float sh_g[100];

    // ---- Phase 0: 16 u3 gates in parallel ----
    if (t < 16) {
        const int blk = t >> 2, j = (t >> 1) & 1, k = t & 1;
        const float* p = qstyles + ((((b * 4 + blk) * 2 + j) * 2 + k) * 3);
        float th = p[0], ph = p[1], la = p[2];
        float ct, st, cl, sl, cp, sp, cpl, spl;
        __sincosf(0.5f * th, &st, &ct);
        __sincosf(la, &sl, &cl);
        __sincosf(ph, &sp, &cp);
        __sincosf(ph + la, &spl, &cpl);
        shU[t][0] = make_float2(ct, 0.f);
        shU[t][1] = make_float2(-cl * st, -sl * st);
        shU[t][2] = make_float2(cp * st, sp * st);
        shU[t][3] = make_float2(cpl * ct, spl * ct);
    }
    __syncthreads();

    // ---- Phase 1: block matrices, one thread per (blk, column) ----
    if (t < 16) {
        const int blk = t >> 2, col = t & 3;
        float2 v[4];
        for (int r = 0; r < 4; ++r)
            v[r] = make_float2(r == col ? 1.f : 0.f, 0.f);
        for (int j = 0; j < 2; ++j) {
            {   // wire 0: row pairs (0,2),(1,3)
                const float2* u = shU[blk * 4 + j * 2 + 0];
                float2 a0 = v[0], a1 = v[1];
                v[0] = cfmac(u[0], a0, cmulc(u[1], v[2]));
                v[2] = cfmac(u[2], a0, cmulc(u[3], v[2]));
                v[1] = cfmac(u[0], a1, cmulc(u[1], v[3]));
                v[3] = cfmac(u[2], a1, cmulc(u[3], v[3]));
            }
            {   // wire 1: row pairs (0,1),(2,3)
                const float2* u = shU[blk * 4 + j * 2 + 1];
                float2 a0 = v[0], a2 = v[2];
                v[0] = cfmac(u[0], a0, cmulc(u[1], v[1]));
                v[1] = cfmac(u[2], a0, cmulc(u[3], v[1]));
                v[2] = cfmac(u[0], a2, cmulc(u[1], v[3]));
                v[3] = cfmac(u[2], a2, cmulc(u[3], v[3]));
            }
            float2 tmp = v[2]; v[2] = v[3]; v[3] = tmp;  // CNOT
        }
        for (int r = 0; r < 4; ++r) shM[blk][r * 4 + col] = v[r];
    }
    __syncthreads();

    // ---- Phase 2: ev on the 7x7 grid (table-driven phases) ----
    if (t < 49) {
        int j = t / 7, kk = t % 7;
        int rp = j + kk;
        int rm = (j - kk + 14) % 14;
        float2 d0 = make_float2(HC[rp], -HS[rp]);
        float2 d1 = make_float2(HC[rm], -HS[rm]);
        float2 d2 = make_float2(d1.x, -d1.y);
        float2 d3 = make_float2(d0.x, -d0.y);
        float2 s[4];
        for (int i = 0; i < 4; ++i) s[i] = shM[0][i * 4 + 0];
        for (int it = 1; it <= 3; ++it) {
            float2 tv[4];
            tv[0] = cmulc(d0, s[0]); tv[1] = cmulc(d1, s[1]);
            tv[2] = cmulc(d2, s[2]); tv[3] = cmulc(d3, s[3]);
            for (int i = 0; i < 4; ++i) {
                float2 acc = cmulc(shM[it][i * 4 + 0], tv[0]);
                for (int kx = 1; kx < 4; ++kx)
                    acc = cfmac(shM[it][i * 4 + kx], tv[kx], acc);
                s[i] = acc;
            }
        }
        sh_ev[t] = (s[0].x * s[0].x + s[0].y * s[0].y)
                 + (s[1].x * s[1].x + s[1].y * s[1].y)
                 - (s[2].x * s[2].x + s[2].y * s[2].y)
                 - (s[3].x * s[3].x + s[3].y * s[3].y);
    }
    __syncthreads();

    // ---- Phase 3: exact 7x7 DFT (incremental mod-7 indexing) ----
    if (t < 25) {
        int m, n;
        if (t < 4) { m = 0; n = t; }
        else       { m = 1 + (t - 4) / 7; n = ((t - 4) % 7) - 3; }
        int n7 = (n + 7) % 7;
        float cr = 0.f, ci = 0.f;
        int rj = 0;
        for (int j = 0; j < 7; ++j) {
            int r = rj;
            for (int kk = 0; kk < 7; ++kk) {
                float e = sh_ev[j * 7 + kk];
                cr = fmaf(e, TWC[r], cr);
                ci = fmaf(e, TWS[r], ci);
                r += n7; if (r >= 7) r -= 7;
            }
            rj += m; if (rj >= 7) rj -= 7;
        }
        sh_c[m][n + 3] = make_float2(cr * (1.f / 49.f), ci * (1.f / 49.f));
    }
    __syncthreads();

    // ---- Phase 4: pack duplicated, sign-baked coefficients into smem ----
#define PUT(idx, val) do { sh_g[2 * (idx)] = (val); sh_g[2 * (idx) + 1] = (val); } while (0)
    if (t == 15) { PUT(0, sh_c[0][3].x); PUT(49, 0.f); }
    if (t < 3) {
        int n = t + 1;
        PUT(1 + 2 * t, 2.f * sh_c[0][3 + n].x);
        PUT(2 + 2 * t, -2.f * sh_c[0][3 + n].y);
    }
    if (t >= 3 && t < 6) {
        int m = t - 2;
        int bs = 7 + 14 * (m - 1);
        PUT(bs + 0, 2.f * sh_c[m][3].x);
        PUT(bs + 1, 2.f * sh_c[m][3].y);
    }
    if (t >= 6 && t < 15) {
        int p = t - 6;
        int m = 1 + p / 3, n = 1 + p % 3;
        int q = 7 + 14 * (m - 1) + 2 + 4 * (n - 1);
        float2 cp = sh_c[m][3 + n], cm = sh_c[m][3 - n];
        PUT(q + 0,  2.f * (cp.x + cm.x));
        PUT(q + 1, -2.f * (cp.y - cm.y));
        PUT(q + 2,  2.f * (cp.y + cm.y));
        PUT(q + 3,  2.f * (cp.x - cm.x));
    }
#undef PUT

    // ---- x loads issued before the final barrier (latency overlaps it) ----
    const float4* xin = reinterpret_cast<const float4*>(x) + (size_t)b * (HW / 2);
    u64* o = reinterpret_cast<u64*>(out) + (size_t)b * (HW / 2);
    const int base = blockIdx.x * 512 + t;
    float4 xv0 = xin[base];
    float4 xv1 = xin[base + 256];

    __syncthreads();

    const u64* C = reinterpret_cast<const u64*>(sh_g);
    o[base]       = eval_pair(xv0, C);
    o[base + 256] = eval_pair(xv1, C);
}

extern "C" void kernel_launch(void* const* d_in, const int* in_sizes, int n_in,
                              void* d_out, int out_size) {
    const float* x  = (const float*)d_in[0];
    const float* qs = (const float*)d_in[1];
    if (n_in >= 2 && in_sizes[0] < in_sizes[1]) {
        x  = (const float*)d_in[1];
        qs = (const float*)d_in[0];
    }

    dim3 grid(HW / (2 * 2 * 256), NB);   // (16, 32) = 512 blocks x 256 thr
    qlayer_fused<<<grid, 256>>>(x, qs, (float*)d_out);
}

// round 9
// speedup vs baseline: 1.7883x; 1.7883x over previous
#include <cuda_runtime.h>
#include <math.h>

#define NB 32
#define HW 16384

typedef unsigned long long u64;

// Packed, sign-baked coefficients: 50 u64 (100 floats) per b, value duplicated
// in both 32-bit halves for f32x2 broadcast.
//  [0] c00
//  [1+2(n-1)] qr_n   [2+2(n-1)] -qi_n                     (n=1..3)
//  base=7+14(m-1): [base] t0r  [base+1] t0i
//  [base+2+4(n-1)+{0..3}] = Pr, -Mi, Pi, Mr               (n=1..3)
//  [49] pad
__device__ __align__(16) float g_coef_pk[NB][100];

__device__ __forceinline__ u64 fma2(u64 a, u64 b, u64 c) {
    u64 d;
    asm("fma.rn.f32x2 %0, %1, %2, %3;" : "=l"(d) : "l"(a), "l"(b), "l"(c));
    return d;
}
__device__ __forceinline__ u64 mul2(u64 a, u64 b) {
    u64 d;
    asm("mul.rn.f32x2 %0, %1, %2;" : "=l"(d) : "l"(a), "l"(b));
    return d;
}
__device__ __forceinline__ u64 add2(u64 a, u64 b) {
    u64 d;
    asm("add.rn.f32x2 %0, %1, %2;" : "=l"(d) : "l"(a), "l"(b));
    return d;
}
__device__ __forceinline__ u64 neg2(u64 a) { return a ^ 0x8000000080000000ull; }
__device__ __forceinline__ u64 pk(float lo, float hi) {
    u64 d;
    asm("mov.b64 %0, {%1, %2};" : "=l"(d) : "f"(lo), "f"(hi));
    return d;
}

__device__ __forceinline__ float2 cmulc(float2 a, float2 b) {
    return make_float2(fmaf(a.x, b.x, -a.y * b.y), fmaf(a.x, b.y, a.y * b.x));
}
__device__ __forceinline__ float2 cfmac(float2 a, float2 b, float2 c) {
    c.x = fmaf(a.x, b.x, fmaf(-a.y, b.y, c.x));
    c.y = fmaf(a.x, b.y, fmaf(a.y, b.x, c.y));
    return c;
}

// cos/sin(pi*r/7), r = 0..13
__constant__ float HC[14] = {
    1.f,  0.90096886790f,  0.62348980185f,  0.22252093396f,
    -0.22252093396f, -0.62348980185f, -0.90096886790f, -1.f,
    -0.90096886790f, -0.62348980185f, -0.22252093396f,
    0.22252093396f,  0.62348980185f,  0.90096886790f };
__constant__ float HS[14] = {
    0.f,  0.43388373912f,  0.78183148246f,  0.97492791218f,
    0.97492791218f,  0.78183148246f,  0.43388373912f,  0.f,
    -0.43388373912f, -0.78183148246f, -0.97492791218f,
    -0.97492791218f, -0.78183148246f, -0.43388373912f };
// twiddle e^{-2*pi*i*k/7}
__constant__ float TWC[7] = {
    1.f, 0.62348980185f, -0.22252093396f, -0.90096886790f,
    -0.90096886790f, -0.22252093396f, 0.62348980185f };
__constant__ float TWS[7] = {
    0.f, -0.78183148246f, -0.97492791218f, -0.43388373912f,
    0.43388373912f, 0.97492791218f, 0.78183148246f };

// ---------------------------------------------------------------------------
// Setup: 32 blocks x 64 threads, table-driven. Uncapped registers (no
// launch_bounds) so the per-thread matrix/DFT state never spills.
// ---------------------------------------------------------------------------
__global__ void setup_kernel(const float* __restrict__ qstyles) {
    const int b = blockIdx.x;
    const int t = threadIdx.x;
    __shared__ float2 shU[16][4];
    __shared__ float2 shM[4][16];
    __shared__ float sh_ev[49];
    __shared__ float2 sh_c[4][7];

    if (t < 16) {
        const int blk = t >> 2, j = (t >> 1) & 1, k = t & 1;
        const float* p = qstyles + ((((b * 4 + blk) * 2 + j) * 2 + k) * 3);
        float th = p[0], ph = p[1], la = p[2];
        float ct, st, cl, sl, cp, sp, cpl, spl;
        __sincosf(0.5f * th, &st, &ct);
        __sincosf(la, &sl, &cl);
        __sincosf(ph, &sp, &cp);
        __sincosf(ph + la, &spl, &cpl);
        shU[t][0] = make_float2(ct, 0.f);
        shU[t][1] = make_float2(-cl * st, -sl * st);
        shU[t][2] = make_float2(cp * st, sp * st);
        shU[t][3] = make_float2(cpl * ct, spl * ct);
    }
    __syncthreads();

    if (t < 16) {
        const int blk = t >> 2, col = t & 3;
        float2 v[4];
        for (int r = 0; r < 4; ++r)
            v[r] = make_float2(r == col ? 1.f : 0.f, 0.f);
        for (int j = 0; j < 2; ++j) {
            {   // wire 0: row pairs (0,2),(1,3)
                const float2* u = shU[blk * 4 + j * 2 + 0];
                float2 a0 = v[0], a1 = v[1];
                v[0] = cfmac(u[0], a0, cmulc(u[1], v[2]));
                v[2] = cfmac(u[2], a0, cmulc(u[3], v[2]));
                v[1] = cfmac(u[0], a1, cmulc(u[1], v[3]));
                v[3] = cfmac(u[2], a1, cmulc(u[3], v[3]));
            }
            {   // wire 1: row pairs (0,1),(2,3)
                const float2* u = shU[blk * 4 + j * 2 + 1];
                float2 a0 = v[0], a2 = v[2];
                v[0] = cfmac(u[0], a0, cmulc(u[1], v[1]));
                v[1] = cfmac(u[2], a0, cmulc(u[3], v[1]));
                v[2] = cfmac(u[0], a2, cmulc(u[1], v[3]));
                v[3] = cfmac(u[2], a2, cmulc(u[3], v[3]));
            }
            float2 tmp = v[2]; v[2] = v[3]; v[3] = tmp;  // CNOT
        }
        for (int r = 0; r < 4; ++r) shM[blk][r * 4 + col] = v[r];
    }
    __syncthreads();

    if (t < 49) {
        int j = t / 7, kk = t % 7;
        int rp = j + kk;
        int rm = (j - kk + 14) % 14;
        float2 d0 = make_float2(HC[rp], -HS[rp]);
        float2 d1 = make_float2(HC[rm], -HS[rm]);
        float2 d2 = make_float2(d1.x, -d1.y);
        float2 d3 = make_float2(d0.x, -d0.y);
        float2 s[4];
        for (int i = 0; i < 4; ++i) s[i] = shM[0][i * 4 + 0];
        for (int it = 1; it <= 3; ++it) {
            float2 tv[4];
            tv[0] = cmulc(d0, s[0]); tv[1] = cmulc(d1, s[1]);
            tv[2] = cmulc(d2, s[2]); tv[3] = cmulc(d3, s[3]);
            for (int i = 0; i < 4; ++i) {
                float2 acc = cmulc(shM[it][i * 4 + 0], tv[0]);
                for (int kx = 1; kx < 4; ++kx)
                    acc = cfmac(shM[it][i * 4 + kx], tv[kx], acc);
                s[i] = acc;
            }
        }
        sh_ev[t] = (s[0].x * s[0].x + s[0].y * s[0].y)
                 + (s[1].x * s[1].x + s[1].y * s[1].y)
                 - (s[2].x * s[2].x + s[2].y * s[2].y)
                 - (s[3].x * s[3].x + s[3].y * s[3].y);
    }
    __syncthreads();

    if (t < 25) {
        int m, n;
        if (t < 4) { m = 0; n = t; }
        else       { m = 1 + (t - 4) / 7; n = ((t - 4) % 7) - 3; }
        int n7 = (n + 7) % 7;
        float cr = 0.f, ci = 0.f;
        int rj = 0;
        for (int j = 0; j < 7; ++j) {
            int r = rj;
            for (int kk = 0; kk < 7; ++kk) {
                float e = sh_ev[j * 7 + kk];
                cr = fmaf(e, TWC[r], cr);
                ci = fmaf(e, TWS[r], ci);
                r += n7; if (r >= 7) r -= 7;
            }
            rj += m; if (rj >= 7) rj -= 7;
        }
        sh_c[m][n + 3] = make_float2(cr * (1.f / 49.f), ci * (1.f / 49.f));
    }
    __syncthreads();

    float* g = g_coef_pk[b];
#define PUT(idx, val) do { g[2 * (idx)] = (val); g[2 * (idx) + 1] = (val); } while (0)
    if (t == 15) { PUT(0, sh_c[0][3].x); PUT(49, 0.f); }
    if (t < 3) {
        int n = t + 1;
        PUT(1 + 2 * t, 2.f * sh_c[0][3 + n].x);
        PUT(2 + 2 * t, -2.f * sh_c[0][3 + n].y);
    }
    if (t >= 3 && t < 6) {
        int m = t - 2;
        int bs = 7 + 14 * (m - 1);
        PUT(bs + 0, 2.f * sh_c[m][3].x);
        PUT(bs + 1, 2.f * sh_c[m][3].y);
    }
    if (t >= 6 && t < 15) {
        int p = t - 6;
        int m = 1 + p / 3, n = 1 + p % 3;
        int q = 7 + 14 * (m - 1) + 2 + 4 * (n - 1);
        float2 cp = sh_c[m][3 + n], cm = sh_c[m][3 - n];
        PUT(q + 0,  2.f * (cp.x + cm.x));
        PUT(q + 1, -2.f * (cp.y - cm.y));
        PUT(q + 2,  2.f * (cp.y + cm.y));
        PUT(q + 3,  2.f * (cp.x - cm.x));
    }
#undef PUT
    // PDL: allow the dependent main kernel's blocks to start.
    cudaTriggerProgrammaticLaunchCompletion();
}

// ---------------------------------------------------------------------------
// Packed evaluation of one element pair; coefficients read from shared mem.
// ---------------------------------------------------------------------------
__device__ __forceinline__ u64 eval_pair(float4 xv, const u64* __restrict__ C) {
    const u64 NEG1 = 0xBF800000BF800000ull;

    float s0a, c0a, s1a, c1a, s0b, c0b, s1b, c1b;
    __sincosf(xv.x, &s0a, &c0a);
    __sincosf(xv.y, &s1a, &c1a);
    __sincosf(xv.z, &s0b, &c0b);
    __sincosf(xv.w, &s1b, &c1b);

    u64 c0 = pk(c0a, c0b), s0 = pk(s0a, s0b);
    u64 c1 = pk(c1a, c1b), s1 = pk(s1a, s1b);

    u64 tc0 = add2(c0, c0), tc1 = add2(c1, c1);
    u64 cw2 = fma2(tc0, c0, NEG1);
    u64 nsw1 = neg2(s0);
    u64 nsw2 = mul2(tc0, nsw1);
    u64 cw3 = fma2(tc0, cw2, neg2(c0));
    u64 nsw3 = fma2(tc0, nsw2, s0);
    u64 cz2 = fma2(tc1, c1, NEG1);
    u64 sz2 = mul2(tc1, s1);
    u64 cz3 = fma2(tc1, cz2, neg2(c1));
    u64 sz3 = fma2(tc1, sz2, neg2(s1));

    u64 cz[3] = {c1, cz2, cz3};
    u64 sz[3] = {s1, sz2, sz3};
    u64 cw[3] = {c0, cw2, cw3};
    u64 nsw[3] = {nsw1, nsw2, nsw3};

    u64 ev0 = C[0];
    u64 ev1 = fma2(C[1], cz[0], mul2(C[2], sz[0]));
#pragma unroll
    for (int n = 1; n < 3; ++n) {
        ev0 = fma2(C[1 + 2 * n], cz[n], ev0);
        ev1 = fma2(C[2 + 2 * n], sz[n], ev1);
    }
#pragma unroll
    for (int m = 0; m < 3; ++m) {
        const int base = 7 + 14 * m;
        u64 hx = C[base], hy = C[base + 1];
#pragma unroll
        for (int n = 0; n < 3; ++n) {
            const int q = base + 2 + 4 * n;
            hx = fma2(C[q + 0], cz[n], hx);
            hx = fma2(C[q + 1], sz[n], hx);
            hy = fma2(C[q + 2], cz[n], hy);
            hy = fma2(C[q + 3], sz[n], hy);
        }
        if (m & 1) { ev1 = fma2(cw[m], hx, ev1); ev1 = fma2(nsw[m], hy, ev1); }
        else       { ev0 = fma2(cw[m], hx, ev0); ev0 = fma2(nsw[m], hy, ev0); }
    }
    return add2(ev0, ev1);
}

// ---------------------------------------------------------------------------
// Main (R5 config, best measured): 256 threads x 512 blocks, 2 packed pairs
// per thread, coefficients staged in shared memory, PDL grid-sync.
// ---------------------------------------------------------------------------
__global__ void __launch_bounds__(256, 4)
qlayer_kernel(const float* __restrict__ x, float* __restrict__ out) {
    const int b = blockIdx.y;
    const int t = threadIdx.x;
    __shared__ __align__(16) float sh_g[100];

    const float4* xin = reinterpret_cast<const float4*>(x) + (size_t)b * (HW / 2);
    u64* o = reinterpret_cast<u64*>(out) + (size_t)b * (HW / 2);
    const int base = blockIdx.x * 512 + t;

    // x loads are independent of setup's output — issue before the grid sync.
    float4 xv0 = xin[base];
    float4 xv1 = xin[base + 256];

    // Wait for setup_kernel's coefficient writes to be visible.
    cudaGridDependencySynchronize();

    if (t < 25)
        reinterpret_cast<float4*>(sh_g)[t] =
            reinterpret_cast<const float4*>(g_coef_pk[b])[t];
    __syncthreads();

    const u64* C = reinterpret_cast<const u64*>(sh_g);
    o[base]       = eval_pair(xv0, C);
    o[base + 256] = eval_pair(xv1, C);
}

extern "C" void kernel_launch(void* const* d_in, const int* in_sizes, int n_in,
                              void* d_out, int out_size) {
    const float* x  = (const float*)d_in[0];
    const float* qs = (const float*)d_in[1];
    if (n_in >= 2 && in_sizes[0] < in_sizes[1]) {
        x  = (const float*)d_in[1];
        qs = (const float*)d_in[0];
    }

    setup_kernel<<<NB, 64>>>(qs);

    // Programmatic Dependent Launch: overlap main's ramp + x loads with setup.
    dim3 grid(HW / (2 * 2 * 256), NB);   // (16, 32) = 512 blocks x 256 thr
    cudaLaunchConfig_t cfg = {};
    cfg.gridDim = grid;
    cfg.blockDim = dim3(256, 1, 1);
    cfg.dynamicSmemBytes = 0;
    cfg.stream = 0;
    cudaLaunchAttribute attrs[1];
    attrs[0].id = cudaLaunchAttributeProgrammaticStreamSerialization;
    attrs[0].val.programmaticStreamSerializationAllowed = 1;
    cfg.attrs = attrs;
    cfg.numAttrs = 1;
    cudaLaunchKernelEx(&cfg, qlayer_kernel, x, (float*)d_out);
}